// round 1
// baseline (speedup 1.0000x reference)
#include <cuda_runtime.h>
#include <cuda_bf16.h>

// ---------------------------------------------------------------------------
// SpatialLiDAREncoder: fused MLP (4->64->128->128, BN+ReLU folded) + BEV
// scatter-max into (B=4, FEAT=128, H=128, W=128).
//
// Plan:
//   1) fuse_kernel: fold BN into weights/biases; store W2/W3 transposed and
//      k-pair interleaved ([k/2][o][2]) in __device__ globals.
//   2) cudaMemsetAsync(d_out, 0): feats are post-ReLU (>=0), empty cells -> 0,
//      so int-reinterpreted atomicMax against 0-init is exact.
//   3) mlp_scatter_kernel: persistent, 1 block/SM, 256 thr = 128 features x
//      2 point-teams, 16 points per chunk. Weights resident in smem.
//      Inner products use packed fma.rn.f32x2 (2 points per instruction).
// ---------------------------------------------------------------------------

#define BATCH    4
#define NPT      120000         // points per batch
#define NPTS_ALL 480000         // B * N
#define FEATC    128
#define HWSZ     16384          // 128*128
#define CHUNK    16
#define NCHUNK   30000          // 480000 / 16  (divides NPT: chunks never span batches)
#define STR      20             // padded point stride in activation staging
#define EPSF     1e-5f

// Fused parameter storage (static device globals -- no allocation).
__device__ float gW1f[64 * 4];     // [o][i], BN-scaled
__device__ float gB1f[64];
__device__ float gW2P[64 * 128];   // [k/2][o][2]
__device__ float gB2f[128];
__device__ float gW3P[128 * 128];  // [k/2][o][2]
__device__ float gB3f[128];

// ---------------------------------------------------------------------------
__global__ void fuse_kernel(
    const float* __restrict__ W1, const float* __restrict__ b1,
    const float* __restrict__ g1, const float* __restrict__ be1,
    const float* __restrict__ m1, const float* __restrict__ v1,
    const float* __restrict__ W2, const float* __restrict__ b2,
    const float* __restrict__ g2, const float* __restrict__ be2,
    const float* __restrict__ m2, const float* __restrict__ v2,
    const float* __restrict__ W3, const float* __restrict__ b3,
    const float* __restrict__ g3, const float* __restrict__ be3,
    const float* __restrict__ m3, const float* __restrict__ v3)
{
    int tid = blockIdx.x * blockDim.x + threadIdx.x;
    int nt  = gridDim.x * blockDim.x;

    for (int i = tid; i < 64 * 4; i += nt) {
        int o = i >> 2;
        float s = g1[o] * rsqrtf(v1[o] + EPSF);
        gW1f[i] = W1[i] * s;
    }
    for (int o = tid; o < 64; o += nt) {
        float s = g1[o] * rsqrtf(v1[o] + EPSF);
        gB1f[o] = (b1[o] - m1[o]) * s + be1[o];
    }
    for (int i = tid; i < 128 * 64; i += nt) {
        int o = i >> 6, k = i & 63;
        float s = g2[o] * rsqrtf(v2[o] + EPSF);
        gW2P[(k >> 1) * 256 + o * 2 + (k & 1)] = W2[i] * s;
    }
    for (int i = tid; i < 128 * 128; i += nt) {
        int o = i >> 7, k = i & 127;
        float s = g3[o] * rsqrtf(v3[o] + EPSF);
        gW3P[(k >> 1) * 256 + o * 2 + (k & 1)] = W3[i] * s;
    }
    for (int o = tid; o < 128; o += nt) {
        float s2 = g2[o] * rsqrtf(v2[o] + EPSF);
        gB2f[o] = (b2[o] - m2[o]) * s2 + be2[o];
        float s3 = g3[o] * rsqrtf(v3[o] + EPSF);
        gB3f[o] = (b3[o] - m3[o]) * s3 + be3[o];
    }
}

// ---------------------------------------------------------------------------
// Packed fp32x2 helpers (Blackwell FFMA2 -- only reachable via PTX).
__device__ __forceinline__ unsigned long long pack2(float x, float y) {
    unsigned long long r;
    asm("mov.b64 %0, {%1, %2};" : "=l"(r) : "f"(x), "f"(y));
    return r;
}
__device__ __forceinline__ float2 unpack2(unsigned long long v) {
    float2 f;
    asm("mov.b64 {%0, %1}, %2;" : "=f"(f.x), "=f"(f.y) : "l"(v));
    return f;
}
__device__ __forceinline__ void ffma2(unsigned long long& acc,
                                      unsigned long long a,
                                      unsigned long long b) {
    asm("fma.rn.f32x2 %0, %1, %2, %0;" : "+l"(acc) : "l"(a), "l"(b));
}

// One dense layer for this thread's feature `o`, its team's 8 points.
// wsm: smem weights [k/2][128][2]; hin: smem activations [k][STR].
template <int NK2>
__device__ __forceinline__ void mlp_layer(const float* __restrict__ wsm,
                                          const float* __restrict__ hin,
                                          int o, int team, float bias,
                                          float* __restrict__ res /*8*/)
{
    unsigned long long bb = pack2(bias, bias);
    unsigned long long a0 = bb, a1 = bb, a2 = bb, a3 = bb;
    const float* hbase = hin + team * 8;
    const float2* w2 = (const float2*)wsm;
#pragma unroll 8
    for (int k2 = 0; k2 < NK2; ++k2) {
        float2 w = w2[k2 * 128 + o];
        unsigned long long wa = pack2(w.x, w.x);
        unsigned long long wb = pack2(w.y, w.y);
        const float* h0 = hbase + (2 * k2) * STR;
        ulonglong2 p0 = *(const ulonglong2*)(h0);            // pts 0-3, row k
        ulonglong2 p1 = *(const ulonglong2*)(h0 + 4);        // pts 4-7, row k
        ulonglong2 q0 = *(const ulonglong2*)(h0 + STR);      // pts 0-3, row k+1
        ulonglong2 q1 = *(const ulonglong2*)(h0 + STR + 4);  // pts 4-7, row k+1
        ffma2(a0, wa, p0.x); ffma2(a1, wa, p0.y);
        ffma2(a2, wa, p1.x); ffma2(a3, wa, p1.y);
        ffma2(a0, wb, q0.x); ffma2(a1, wb, q0.y);
        ffma2(a2, wb, q1.x); ffma2(a3, wb, q1.y);
    }
    float2 f;
    f = unpack2(a0); res[0] = fmaxf(f.x, 0.f); res[1] = fmaxf(f.y, 0.f);
    f = unpack2(a1); res[2] = fmaxf(f.x, 0.f); res[3] = fmaxf(f.y, 0.f);
    f = unpack2(a2); res[4] = fmaxf(f.x, 0.f); res[5] = fmaxf(f.y, 0.f);
    f = unpack2(a3); res[6] = fmaxf(f.x, 0.f); res[7] = fmaxf(f.y, 0.f);
}

// ---------------------------------------------------------------------------
// Shared memory layout (floats):
//   w2p  [0, 8192)        w3p [8192, 24576)
//   w1f  [24576, 24832)   b1f [24832, 24896)
//   h1s  [24896, +64*STR) h2s [.., +128*STR)
//   pts  (16 float4)      cell (16 int)
#define SM_W2P 0
#define SM_W3P 8192
#define SM_W1F 24576
#define SM_B1F 24832
#define SM_H1S 24896
#define SM_H2S (SM_H1S + 64 * STR)      // 26176
#define SM_PTS (SM_H2S + 128 * STR)     // 28736
#define SM_CEL (SM_PTS + 64)            // 28800
#define SM_FLOATS (SM_CEL + 16)         // 28816
#define SMEM_BYTES (SM_FLOATS * 4)      // 115264

__global__ void __launch_bounds__(256, 1)
mlp_scatter_kernel(const float4* __restrict__ ptsg, float* __restrict__ out)
{
    extern __shared__ float sm[];
    float* w2p = sm + SM_W2P;
    float* w3p = sm + SM_W3P;
    float* w1f = sm + SM_W1F;
    float* b1f = sm + SM_B1F;
    float* h1s = sm + SM_H1S;
    float* h2s = sm + SM_H2S;
    float4* pts = (float4*)(sm + SM_PTS);
    int*   cell = (int*)(sm + SM_CEL);

    const int t = threadIdx.x;

    // Stage fused weights into smem (once per block; block is persistent).
    for (int i = t; i < 8192;  i += 256) w2p[i] = gW2P[i];
    for (int i = t; i < 16384; i += 256) w3p[i] = gW3P[i];
    if (t < 256) w1f[t] = gW1f[t];
    if (t < 64)  b1f[t] = gB1f[t];

    const int o    = t & 127;    // output feature
    const int team = t >> 7;     // point sub-group (8 points each)
    const float b2v = gB2f[o];
    const float b3v = gB3f[o];
    __syncthreads();

    for (int c = blockIdx.x; c < NCHUNK; c += gridDim.x) {
        const int gp = c * CHUNK;

        // -- load points, compute cell offsets -------------------------------
        if (t < CHUNK) {
            float4 p = ptsg[gp + t];
            pts[t] = p;
            float xn = (p.x + 50.f) / 100.f;
            float yn = (p.y + 50.f) / 100.f;
            bool valid = (xn >= 0.f) & (xn <= 1.f) & (yn >= 0.f) & (yn <= 1.f);
            int gx = min(max((int)(xn * 127.f), 0), 127);
            int gy = min(max((int)(yn * 127.f), 0), 127);
            int b  = gp / NPT;                 // chunk never spans batches
            cell[t] = valid ? (b * (FEATC * HWSZ) + gy * 128 + gx) : -1;
        }
        __syncthreads();

        // -- layer 1: 4 -> 64 ------------------------------------------------
        {
            int p  = t & 15;
            int ob = t >> 4;
            float4 pv = pts[p];
#pragma unroll
            for (int r = 0; r < 4; ++r) {
                int oo = ob + 16 * r;
                const float* w = &w1f[oo * 4];
                float s = b1f[oo] + pv.x * w[0] + pv.y * w[1]
                                  + pv.z * w[2] + pv.w * w[3];
                h1s[oo * STR + p] = fmaxf(s, 0.f);
            }
        }
        __syncthreads();

        // -- layer 2: 64 -> 128 ---------------------------------------------
        {
            float r2[8];
            mlp_layer<32>(w2p, h1s, o, team, b2v, r2);
            float* dst = &h2s[o * STR + team * 8];
#pragma unroll
            for (int j = 0; j < 8; ++j) dst[j] = r2[j];
        }
        __syncthreads();

        // -- layer 3: 128 -> 128, then scatter-max ---------------------------
        {
            float r3[8];
            mlp_layer<64>(w3p, h2s, o, team, b3v, r3);
            float* outo = out + (size_t)o * HWSZ;
#pragma unroll
            for (int j = 0; j < 8; ++j) {
                int cb = cell[team * 8 + j];
                if (cb >= 0)
                    atomicMax((int*)(outo + cb), __float_as_int(r3[j]));
            }
        }
        __syncthreads();  // protect pts/cell/h1s/h2s before next chunk
    }
}

// ---------------------------------------------------------------------------
extern "C" void kernel_launch(void* const* d_in, const int* in_sizes, int n_in,
                              void* d_out, int out_size)
{
    (void)in_sizes; (void)n_in;
    const float* points = (const float*)d_in[0];

    // Zero BEV output (feats >= 0; empty cells must be 0).
    cudaMemsetAsync(d_out, 0, (size_t)out_size * sizeof(float), 0);

    fuse_kernel<<<32, 256>>>(
        (const float*)d_in[1],  (const float*)d_in[2],  (const float*)d_in[3],
        (const float*)d_in[4],  (const float*)d_in[5],  (const float*)d_in[6],
        (const float*)d_in[7],  (const float*)d_in[8],  (const float*)d_in[9],
        (const float*)d_in[10], (const float*)d_in[11], (const float*)d_in[12],
        (const float*)d_in[13], (const float*)d_in[14], (const float*)d_in[15],
        (const float*)d_in[16], (const float*)d_in[17], (const float*)d_in[18]);

    int dev = 0;
    cudaGetDevice(&dev);
    int nsm = 0;
    cudaDeviceGetAttribute(&nsm, cudaDevAttrMultiProcessorCount, dev);
    if (nsm <= 0) nsm = 148;

    cudaFuncSetAttribute(mlp_scatter_kernel,
                         cudaFuncAttributeMaxDynamicSharedMemorySize,
                         SMEM_BYTES);
    mlp_scatter_kernel<<<nsm, 256, SMEM_BYTES>>>((const float4*)points,
                                                 (float*)d_out);
}

// round 4
// speedup vs baseline: 1.1374x; 1.1374x over previous
#include <cuda_runtime.h>
#include <cuda_bf16.h>

// ---------------------------------------------------------------------------
// SpatialLiDAREncoder round 2: register-tiled fused MLP + BEV scatter-max.
//
//  - fuse_kernel folds BN into weights/biases; W2/W3 stored permuted
//    [k][og][r] (og = o&15, r = o>>4) so each thread's 8 output weights for a
//    given k are 8 contiguous floats = 2x LDS.128, already paired for f32x2.
//  - main kernel: 512 threads/block, 1 block/SM (persistent), chunk = 128
//    points. Per-thread tile 4 points x 8 outputs, accumulators packed
//    f32x2 over output pairs. Activations staged in smem, broadcast loads.
//  - scatter: atomicMax on int bit-pattern (feats are post-ReLU >= 0),
//    output zero-initialized via cudaMemsetAsync.
// ---------------------------------------------------------------------------

#define NPT      120000
#define NALL     480000
#define HWSZ     16384
#define BSTRIDE  (128 * HWSZ)     // 2097152
#define CHUNK    128
#define NCHUNK   3750             // 480000 / 128
#define H1STR    132              // padded row stride (floats)
#define H2STR    132
#define EPSF     1e-5f

typedef unsigned long long ull;

// Fused parameter storage (device globals -- no allocation).
__device__ float gW1f[256];       // [o][i] BN-scaled, o<64
__device__ float gB1f[64];
__device__ float gW2s[64 * 128];  // [k][og*8+r] = W2f[r*16+og][k]
__device__ float gB2s[128];       // [og*8+r]
__device__ float gW3s[128 * 128]; // [k][og*8+r] = W3f[r*16+og][k]
__device__ float gB3s[128];

// ---------------------------------------------------------------------------
__global__ void fuse_kernel(
    const float* __restrict__ W1, const float* __restrict__ b1,
    const float* __restrict__ g1, const float* __restrict__ be1,
    const float* __restrict__ m1, const float* __restrict__ v1,
    const float* __restrict__ W2, const float* __restrict__ b2,
    const float* __restrict__ g2, const float* __restrict__ be2,
    const float* __restrict__ m2, const float* __restrict__ v2,
    const float* __restrict__ W3, const float* __restrict__ b3,
    const float* __restrict__ g3, const float* __restrict__ be3,
    const float* __restrict__ m3, const float* __restrict__ v3)
{
    int tid = blockIdx.x * blockDim.x + threadIdx.x;
    int nt  = gridDim.x * blockDim.x;

    for (int i = tid; i < 256; i += nt) {
        int o = i >> 2;
        gW1f[i] = W1[i] * (g1[o] * rsqrtf(v1[o] + EPSF));
    }
    for (int o = tid; o < 64; o += nt) {
        float s = g1[o] * rsqrtf(v1[o] + EPSF);
        gB1f[o] = (b1[o] - m1[o]) * s + be1[o];
    }
    for (int i = tid; i < 128 * 64; i += nt) {
        int o = i >> 6, k = i & 63;
        float s = g2[o] * rsqrtf(v2[o] + EPSF);
        gW2s[k * 128 + (o & 15) * 8 + (o >> 4)] = W2[i] * s;
    }
    for (int i = tid; i < 128 * 128; i += nt) {
        int o = i >> 7, k = i & 127;
        float s = g3[o] * rsqrtf(v3[o] + EPSF);
        gW3s[k * 128 + (o & 15) * 8 + (o >> 4)] = W3[i] * s;
    }
    for (int o = tid; o < 128; o += nt) {
        float s2 = g2[o] * rsqrtf(v2[o] + EPSF);
        gB2s[(o & 15) * 8 + (o >> 4)] = (b2[o] - m2[o]) * s2 + be2[o];
        float s3 = g3[o] * rsqrtf(v3[o] + EPSF);
        gB3s[(o & 15) * 8 + (o >> 4)] = (b3[o] - m3[o]) * s3 + be3[o];
    }
}

// ---------------------------------------------------------------------------
__device__ __forceinline__ ull pk2(float x, float y) {
    ull r; asm("mov.b64 %0, {%1, %2};" : "=l"(r) : "f"(x), "f"(y)); return r;
}
__device__ __forceinline__ float2 up2(ull v) {
    float2 f; asm("mov.b64 {%0, %1}, %2;" : "=f"(f.x), "=f"(f.y) : "l"(v));
    return f;
}
__device__ __forceinline__ void fma2(ull& a, ull x, ull y) {
    asm("fma.rn.f32x2 %0, %1, %2, %0;" : "+l"(a) : "l"(x), "l"(y));
}

// Shared memory layout (float offsets)
#define SM_W2 0
#define SM_W3 8192
#define SM_W1 24576
#define SM_B1 24832
#define SM_B2 24896
#define SM_B3 25024
#define SM_H1 25152
#define SM_H2 (SM_H1 + 64 * H1STR)    // 33600
#define SM_PT (SM_H2 + 128 * H2STR)   // 50496
#define SM_CL (SM_PT + 512)           // 51008
#define SM_TOT (SM_CL + 128)          // 51136
#define SMEM_BYTES (SM_TOT * 4)       // 204544

__global__ void __launch_bounds__(512, 1)
mlp_scatter_kernel(const float4* __restrict__ ptsg, float* __restrict__ out)
{
    extern __shared__ float sm[];
    float* w2s = sm + SM_W2;
    float* w3s = sm + SM_W3;
    float* w1s = sm + SM_W1;
    float* b1s = sm + SM_B1;
    float* b2s = sm + SM_B2;
    float* b3s = sm + SM_B3;
    float* h1  = sm + SM_H1;
    float* h2  = sm + SM_H2;
    float4* ptsS = (float4*)(sm + SM_PT);
    int*    cellS = (int*)(sm + SM_CL);

    const int t = threadIdx.x;

    // Stage fused weights (block is persistent; done once).
    for (int i = t; i < 8192;  i += 512) w2s[i] = gW2s[i];
    for (int i = t; i < 16384; i += 512) w3s[i] = gW3s[i];
    if (t < 256) w1s[t] = gW1f[t];
    if (t < 64)  b1s[t] = gB1f[t];
    if (t < 128) { b2s[t] = gB2s[t]; b3s[t] = gB3s[t]; }
    __syncthreads();

    const int og = t & 15;        // output group: o = r*16 + og, r = 0..7
    const int pg = t >> 4;        // point group: points pg*4 .. pg*4+3
    ull bias2[4], bias3[4];
#pragma unroll
    for (int j = 0; j < 4; ++j) {
        bias2[j] = *(const ull*)(b2s + og * 8 + 2 * j);
        bias3[j] = *(const ull*)(b3s + og * 8 + 2 * j);
    }
    const int p1  = t & 127;          // layer1: this thread's point
    const int ob1 = (t >> 7) * 16;    // layer1: output base (16 outputs)

    const float* w2p = w2s + og * 8;
    const float* w3p = w3s + og * 8;
    const float* h1p = h1 + pg * 4;
    const float* h2p = h2 + pg * 4;

    for (int c = blockIdx.x; c < NCHUNK; c += gridDim.x) {
        const int gp = c * CHUNK;

        // -- stage points + cell offsets ------------------------------------
        if (t < CHUNK) {
            float4 p = ptsg[gp + t];
            ptsS[t] = p;
            float xn = (p.x + 50.f) * 0.01f;
            float yn = (p.y + 50.f) * 0.01f;
            bool valid = (xn >= 0.f) && (xn <= 1.f) && (yn >= 0.f) && (yn <= 1.f);
            int gx = min(max((int)(xn * 127.f), 0), 127);
            int gy = min(max((int)(yn * 127.f), 0), 127);
            int b  = (gp + t) / NPT;
            cellS[t] = valid ? b * BSTRIDE + gy * 128 + gx : -1;
        }
        __syncthreads();

        // -- layer 1: 4 -> 64 ------------------------------------------------
        {
            float4 pv = ptsS[p1];
#pragma unroll
            for (int r = 0; r < 16; ++r) {
                int o = ob1 + r;
                float4 w = *(const float4*)(w1s + o * 4);
                float s = b1s[o] + pv.x * w.x + pv.y * w.y
                                 + pv.z * w.z + pv.w * w.w;
                h1[o * H1STR + p1] = fmaxf(s, 0.f);
            }
        }
        __syncthreads();

        // -- layer 2: 64 -> 128 (tile 4p x 8o, f32x2 over output pairs) -----
        ull acc[16];
#pragma unroll
        for (int p = 0; p < 4; ++p)
#pragma unroll
            for (int j = 0; j < 4; ++j) acc[p * 4 + j] = bias2[j];

#pragma unroll 8
        for (int k = 0; k < 64; ++k) {
            ulonglong2 wa = *(const ulonglong2*)(w2p + k * 128);
            ulonglong2 wb = *(const ulonglong2*)(w2p + k * 128 + 4);
            float4 h = *(const float4*)(h1p + k * H1STR);
            ull hx = pk2(h.x, h.x), hy = pk2(h.y, h.y);
            ull hz = pk2(h.z, h.z), hw = pk2(h.w, h.w);
            fma2(acc[0],  hx, wa.x); fma2(acc[1],  hx, wa.y);
            fma2(acc[2],  hx, wb.x); fma2(acc[3],  hx, wb.y);
            fma2(acc[4],  hy, wa.x); fma2(acc[5],  hy, wa.y);
            fma2(acc[6],  hy, wb.x); fma2(acc[7],  hy, wb.y);
            fma2(acc[8],  hz, wa.x); fma2(acc[9],  hz, wa.y);
            fma2(acc[10], hz, wb.x); fma2(acc[11], hz, wb.y);
            fma2(acc[12], hw, wa.x); fma2(acc[13], hw, wa.y);
            fma2(acc[14], hw, wb.x); fma2(acc[15], hw, wb.y);
        }
        // epilogue: ReLU + store h2 rows [o = r*16+og], 4 points per float4
        {
            float vals[4][8];
#pragma unroll
            for (int p = 0; p < 4; ++p)
#pragma unroll
                for (int j = 0; j < 4; ++j) {
                    float2 v = up2(acc[p * 4 + j]);
                    vals[p][2 * j]     = fmaxf(v.x, 0.f);
                    vals[p][2 * j + 1] = fmaxf(v.y, 0.f);
                }
#pragma unroll
            for (int r = 0; r < 8; ++r) {
                float4 v = make_float4(vals[0][r], vals[1][r],
                                       vals[2][r], vals[3][r]);
                *(float4*)(h2 + (r * 16 + og) * H2STR + pg * 4) = v;
            }
        }
        __syncthreads();

        // -- layer 3: 128 -> 128 + scatter-max ------------------------------
#pragma unroll
        for (int p = 0; p < 4; ++p)
#pragma unroll
            for (int j = 0; j < 4; ++j) acc[p * 4 + j] = bias3[j];

#pragma unroll 8
        for (int k = 0; k < 128; ++k) {
            ulonglong2 wa = *(const ulonglong2*)(w3p + k * 128);
            ulonglong2 wb = *(const ulonglong2*)(w3p + k * 128 + 4);
            float4 h = *(const float4*)(h2p + k * H2STR);
            ull hx = pk2(h.x, h.x), hy = pk2(h.y, h.y);
            ull hz = pk2(h.z, h.z), hw = pk2(h.w, h.w);
            fma2(acc[0],  hx, wa.x); fma2(acc[1],  hx, wa.y);
            fma2(acc[2],  hx, wb.x); fma2(acc[3],  hx, wb.y);
            fma2(acc[4],  hy, wa.x); fma2(acc[5],  hy, wa.y);
            fma2(acc[6],  hy, wb.x); fma2(acc[7],  hy, wb.y);
            fma2(acc[8],  hz, wa.x); fma2(acc[9],  hz, wa.y);
            fma2(acc[10], hz, wb.x); fma2(acc[11], hz, wb.y);
            fma2(acc[12], hw, wa.x); fma2(acc[13], hw, wa.y);
            fma2(acc[14], hw, wb.x); fma2(acc[15], hw, wb.y);
        }
        {
            int cells[4];
#pragma unroll
            for (int p = 0; p < 4; ++p) cells[p] = cellS[pg * 4 + p];
#pragma unroll
            for (int p = 0; p < 4; ++p) {
                if (cells[p] < 0) continue;
                float* ob = out + cells[p];
#pragma unroll
                for (int j = 0; j < 4; ++j) {
                    float2 v = up2(acc[p * 4 + j]);
                    atomicMax((int*)(ob + ((2 * j) * 16 + og) * HWSZ),
                              __float_as_int(fmaxf(v.x, 0.f)));
                    atomicMax((int*)(ob + ((2 * j + 1) * 16 + og) * HWSZ),
                              __float_as_int(fmaxf(v.y, 0.f)));
                }
            }
        }
        __syncthreads();   // protect pts/cell/h1/h2 before next chunk
    }
}

// ---------------------------------------------------------------------------
extern "C" void kernel_launch(void* const* d_in, const int* in_sizes, int n_in,
                              void* d_out, int out_size)
{
    (void)in_sizes; (void)n_in;
    const float* points = (const float*)d_in[0];

    cudaMemsetAsync(d_out, 0, (size_t)out_size * sizeof(float), 0);

    fuse_kernel<<<32, 256>>>(
        (const float*)d_in[1],  (const float*)d_in[2],  (const float*)d_in[3],
        (const float*)d_in[4],  (const float*)d_in[5],  (const float*)d_in[6],
        (const float*)d_in[7],  (const float*)d_in[8],  (const float*)d_in[9],
        (const float*)d_in[10], (const float*)d_in[11], (const float*)d_in[12],
        (const float*)d_in[13], (const float*)d_in[14], (const float*)d_in[15],
        (const float*)d_in[16], (const float*)d_in[17], (const float*)d_in[18]);

    int dev = 0;
    cudaGetDevice(&dev);
    int nsm = 0;
    cudaDeviceGetAttribute(&nsm, cudaDevAttrMultiProcessorCount, dev);
    if (nsm <= 0) nsm = 148;

    cudaFuncSetAttribute(mlp_scatter_kernel,
                         cudaFuncAttributeMaxDynamicSharedMemorySize,
                         SMEM_BYTES);
    mlp_scatter_kernel<<<nsm, 512, SMEM_BYTES>>>((const float4*)points,
                                                 (float*)d_out);
}

// round 5
// speedup vs baseline: 1.6219x; 1.4260x over previous
#include <cuda_runtime.h>
#include <cuda_bf16.h>

// ---------------------------------------------------------------------------
// SpatialLiDAREncoder round 5: register-tiled fused MLP + BEV scatter-max,
// bank-conflict-free weight layout.
//
//  - Weights for thread og split into wA[k][og*4 + r] (r=0..3) and
//    wB[k][og*4 + r-4] (r=4..7): lane stride 16B -> each 8-lane LDS.128
//    phase covers banks 0..31 exactly once (was 32B stride = 2-way conflict).
//  - main kernel: 512 thr/block, 1 block/SM persistent, chunk = 128 points,
//    per-thread tile 4 points x 8 outputs, f32x2 accumulators over o-pairs.
//  - scatter: atomicMax on int bit-pattern (post-ReLU feats >= 0), output
//    zeroed via cudaMemsetAsync.
// ---------------------------------------------------------------------------

#define NPT      120000
#define NALL     480000
#define HWSZ     16384
#define BSTRIDE  (128 * HWSZ)     // 2097152
#define CHUNK    128
#define NCHUNK   3750             // 480000 / 128
#define H1STR    132
#define H2STR    132
#define EPSF     1e-5f

typedef unsigned long long ull;

// Fused parameter storage (device globals -- no allocation).
__device__ float gW1f[256];        // [o][i] BN-scaled, o<64
__device__ float gB1f[64];
__device__ float gW2a[64 * 64];    // [k][og*4 + r],     r=0..3  (o = r*16+og)
__device__ float gW2b[64 * 64];    // [k][og*4 + r-4],   r=4..7
__device__ float gB2s[128];        // [og*8 + r]
__device__ float gW3a[128 * 64];
__device__ float gW3b[128 * 64];
__device__ float gB3s[128];

// ---------------------------------------------------------------------------
__global__ void fuse_kernel(
    const float* __restrict__ W1, const float* __restrict__ b1,
    const float* __restrict__ g1, const float* __restrict__ be1,
    const float* __restrict__ m1, const float* __restrict__ v1,
    const float* __restrict__ W2, const float* __restrict__ b2,
    const float* __restrict__ g2, const float* __restrict__ be2,
    const float* __restrict__ m2, const float* __restrict__ v2,
    const float* __restrict__ W3, const float* __restrict__ b3,
    const float* __restrict__ g3, const float* __restrict__ be3,
    const float* __restrict__ m3, const float* __restrict__ v3)
{
    int tid = blockIdx.x * blockDim.x + threadIdx.x;
    int nt  = gridDim.x * blockDim.x;

    for (int i = tid; i < 256; i += nt) {
        int o = i >> 2;
        gW1f[i] = W1[i] * (g1[o] * rsqrtf(v1[o] + EPSF));
    }
    for (int o = tid; o < 64; o += nt) {
        float s = g1[o] * rsqrtf(v1[o] + EPSF);
        gB1f[o] = (b1[o] - m1[o]) * s + be1[o];
    }
    for (int i = tid; i < 128 * 64; i += nt) {
        int o = i >> 6, k = i & 63;
        float s = g2[o] * rsqrtf(v2[o] + EPSF);
        int r = o >> 4, og = o & 15;
        float v = W2[i] * s;
        if (r < 4) gW2a[k * 64 + og * 4 + r]     = v;
        else       gW2b[k * 64 + og * 4 + r - 4] = v;
    }
    for (int i = tid; i < 128 * 128; i += nt) {
        int o = i >> 7, k = i & 127;
        float s = g3[o] * rsqrtf(v3[o] + EPSF);
        int r = o >> 4, og = o & 15;
        float v = W3[i] * s;
        if (r < 4) gW3a[k * 64 + og * 4 + r]     = v;
        else       gW3b[k * 64 + og * 4 + r - 4] = v;
    }
    for (int o = tid; o < 128; o += nt) {
        int r = o >> 4, og = o & 15;
        float s2 = g2[o] * rsqrtf(v2[o] + EPSF);
        gB2s[og * 8 + r] = (b2[o] - m2[o]) * s2 + be2[o];
        float s3 = g3[o] * rsqrtf(v3[o] + EPSF);
        gB3s[og * 8 + r] = (b3[o] - m3[o]) * s3 + be3[o];
    }
}

// ---------------------------------------------------------------------------
__device__ __forceinline__ ull pk2(float x, float y) {
    ull r; asm("mov.b64 %0, {%1, %2};" : "=l"(r) : "f"(x), "f"(y)); return r;
}
__device__ __forceinline__ float2 up2(ull v) {
    float2 f; asm("mov.b64 {%0, %1}, %2;" : "=f"(f.x), "=f"(f.y) : "l"(v));
    return f;
}
__device__ __forceinline__ void fma2(ull& a, ull x, ull y) {
    asm("fma.rn.f32x2 %0, %1, %2, %0;" : "+l"(a) : "l"(x), "l"(y));
}

// Shared memory layout (float offsets)
#define SM_W2A 0
#define SM_W2B 4096
#define SM_W3A 8192
#define SM_W3B 16384
#define SM_W1  24576
#define SM_B1  24832
#define SM_B2  24896
#define SM_B3  25024
#define SM_H1  25152
#define SM_H2  (SM_H1 + 64 * H1STR)    // 33600
#define SM_PT  (SM_H2 + 128 * H2STR)   // 50496
#define SM_CL  (SM_PT + 512)           // 51008
#define SM_TOT (SM_CL + 128)           // 51136
#define SMEM_BYTES (SM_TOT * 4)        // 204544

__global__ void __launch_bounds__(512, 1)
mlp_scatter_kernel(const float4* __restrict__ ptsg, float* __restrict__ out)
{
    extern __shared__ float sm[];
    float* w2a = sm + SM_W2A;
    float* w2b = sm + SM_W2B;
    float* w3a = sm + SM_W3A;
    float* w3b = sm + SM_W3B;
    float* w1s = sm + SM_W1;
    float* b1s = sm + SM_B1;
    float* b2s = sm + SM_B2;
    float* b3s = sm + SM_B3;
    float* h1  = sm + SM_H1;
    float* h2  = sm + SM_H2;
    float4* ptsS  = (float4*)(sm + SM_PT);
    int*    cellS = (int*)(sm + SM_CL);

    const int t = threadIdx.x;

    // Stage fused weights (block is persistent; done once).
    for (int i = t; i < 4096; i += 512) { w2a[i] = gW2a[i]; w2b[i] = gW2b[i]; }
    for (int i = t; i < 8192; i += 512) { w3a[i] = gW3a[i]; w3b[i] = gW3b[i]; }
    if (t < 256) w1s[t] = gW1f[t];
    if (t < 64)  b1s[t] = gB1f[t];
    if (t < 128) { b2s[t] = gB2s[t]; b3s[t] = gB3s[t]; }
    __syncthreads();

    const int og = t & 15;        // output group: o = r*16 + og, r = 0..7
    const int pg = t >> 4;        // point group: points pg*4 .. pg*4+3
    ull bias2[4], bias3[4];
#pragma unroll
    for (int j = 0; j < 4; ++j) {
        bias2[j] = *(const ull*)(b2s + og * 8 + 2 * j);
        bias3[j] = *(const ull*)(b3s + og * 8 + 2 * j);
    }
    const int p1  = t & 127;          // layer1: this thread's point
    const int ob1 = (t >> 7) * 16;    // layer1: output base (16 outputs)

    const float* w2ap = w2a + og * 4;
    const float* w2bp = w2b + og * 4;
    const float* w3ap = w3a + og * 4;
    const float* w3bp = w3b + og * 4;
    const float* h1p  = h1 + pg * 4;
    const float* h2p  = h2 + pg * 4;

    for (int c = blockIdx.x; c < NCHUNK; c += gridDim.x) {
        const int gp = c * CHUNK;

        // -- stage points + cell offsets ------------------------------------
        if (t < CHUNK) {
            float4 p = ptsg[gp + t];
            ptsS[t] = p;
            float xn = (p.x + 50.f) * 0.01f;
            float yn = (p.y + 50.f) * 0.01f;
            bool valid = (xn >= 0.f) && (xn <= 1.f) && (yn >= 0.f) && (yn <= 1.f);
            int gx = min(max((int)(xn * 127.f), 0), 127);
            int gy = min(max((int)(yn * 127.f), 0), 127);
            int b  = (gp + t) / NPT;
            cellS[t] = valid ? b * BSTRIDE + gy * 128 + gx : -1;
        }
        __syncthreads();

        // -- layer 1: 4 -> 64 ------------------------------------------------
        {
            float4 pv = ptsS[p1];
#pragma unroll
            for (int r = 0; r < 16; ++r) {
                int o = ob1 + r;
                float4 w = *(const float4*)(w1s + o * 4);
                float s = b1s[o] + pv.x * w.x + pv.y * w.y
                                 + pv.z * w.z + pv.w * w.w;
                h1[o * H1STR + p1] = fmaxf(s, 0.f);
            }
        }
        __syncthreads();

        // -- layer 2: 64 -> 128 (tile 4p x 8o, f32x2 over output pairs) -----
        ull acc[16];
#pragma unroll
        for (int p = 0; p < 4; ++p)
#pragma unroll
            for (int j = 0; j < 4; ++j) acc[p * 4 + j] = bias2[j];

#pragma unroll 8
        for (int k = 0; k < 64; ++k) {
            ulonglong2 wa = *(const ulonglong2*)(w2ap + k * 64);
            ulonglong2 wb = *(const ulonglong2*)(w2bp + k * 64);
            float4 h = *(const float4*)(h1p + k * H1STR);
            ull hx = pk2(h.x, h.x), hy = pk2(h.y, h.y);
            ull hz = pk2(h.z, h.z), hw = pk2(h.w, h.w);
            fma2(acc[0],  hx, wa.x); fma2(acc[1],  hx, wa.y);
            fma2(acc[2],  hx, wb.x); fma2(acc[3],  hx, wb.y);
            fma2(acc[4],  hy, wa.x); fma2(acc[5],  hy, wa.y);
            fma2(acc[6],  hy, wb.x); fma2(acc[7],  hy, wb.y);
            fma2(acc[8],  hz, wa.x); fma2(acc[9],  hz, wa.y);
            fma2(acc[10], hz, wb.x); fma2(acc[11], hz, wb.y);
            fma2(acc[12], hw, wa.x); fma2(acc[13], hw, wa.y);
            fma2(acc[14], hw, wb.x); fma2(acc[15], hw, wb.y);
        }
        // epilogue: ReLU + store h2 rows [o = r*16+og], 4 points per float4
        {
            float vals[4][8];
#pragma unroll
            for (int p = 0; p < 4; ++p)
#pragma unroll
                for (int j = 0; j < 4; ++j) {
                    float2 v = up2(acc[p * 4 + j]);
                    vals[p][2 * j]     = fmaxf(v.x, 0.f);
                    vals[p][2 * j + 1] = fmaxf(v.y, 0.f);
                }
#pragma unroll
            for (int r = 0; r < 8; ++r) {
                float4 v = make_float4(vals[0][r], vals[1][r],
                                       vals[2][r], vals[3][r]);
                *(float4*)(h2 + (r * 16 + og) * H2STR + pg * 4) = v;
            }
        }
        __syncthreads();

        // -- layer 3: 128 -> 128 + scatter-max ------------------------------
#pragma unroll
        for (int p = 0; p < 4; ++p)
#pragma unroll
            for (int j = 0; j < 4; ++j) acc[p * 4 + j] = bias3[j];

#pragma unroll 8
        for (int k = 0; k < 128; ++k) {
            ulonglong2 wa = *(const ulonglong2*)(w3ap + k * 64);
            ulonglong2 wb = *(const ulonglong2*)(w3bp + k * 64);
            float4 h = *(const float4*)(h2p + k * H2STR);
            ull hx = pk2(h.x, h.x), hy = pk2(h.y, h.y);
            ull hz = pk2(h.z, h.z), hw = pk2(h.w, h.w);
            fma2(acc[0],  hx, wa.x); fma2(acc[1],  hx, wa.y);
            fma2(acc[2],  hx, wb.x); fma2(acc[3],  hx, wb.y);
            fma2(acc[4],  hy, wa.x); fma2(acc[5],  hy, wa.y);
            fma2(acc[6],  hy, wb.x); fma2(acc[7],  hy, wb.y);
            fma2(acc[8],  hz, wa.x); fma2(acc[9],  hz, wa.y);
            fma2(acc[10], hz, wb.x); fma2(acc[11], hz, wb.y);
            fma2(acc[12], hw, wa.x); fma2(acc[13], hw, wa.y);
            fma2(acc[14], hw, wb.x); fma2(acc[15], hw, wb.y);
        }
        {
            int cells[4];
#pragma unroll
            for (int p = 0; p < 4; ++p) cells[p] = cellS[pg * 4 + p];
#pragma unroll
            for (int p = 0; p < 4; ++p) {
                if (cells[p] < 0) continue;
                float* ob = out + cells[p];
#pragma unroll
                for (int j = 0; j < 4; ++j) {
                    float2 v = up2(acc[p * 4 + j]);
                    atomicMax((int*)(ob + ((2 * j) * 16 + og) * HWSZ),
                              __float_as_int(fmaxf(v.x, 0.f)));
                    atomicMax((int*)(ob + ((2 * j + 1) * 16 + og) * HWSZ),
                              __float_as_int(fmaxf(v.y, 0.f)));
                }
            }
        }
        __syncthreads();   // protect pts/cell/h1/h2 before next chunk
    }
}

// ---------------------------------------------------------------------------
extern "C" void kernel_launch(void* const* d_in, const int* in_sizes, int n_in,
                              void* d_out, int out_size)
{
    (void)in_sizes; (void)n_in;
    const float* points = (const float*)d_in[0];

    cudaMemsetAsync(d_out, 0, (size_t)out_size * sizeof(float), 0);

    fuse_kernel<<<32, 256>>>(
        (const float*)d_in[1],  (const float*)d_in[2],  (const float*)d_in[3],
        (const float*)d_in[4],  (const float*)d_in[5],  (const float*)d_in[6],
        (const float*)d_in[7],  (const float*)d_in[8],  (const float*)d_in[9],
        (const float*)d_in[10], (const float*)d_in[11], (const float*)d_in[12],
        (const float*)d_in[13], (const float*)d_in[14], (const float*)d_in[15],
        (const float*)d_in[16], (const float*)d_in[17], (const float*)d_in[18]);

    int dev = 0;
    cudaGetDevice(&dev);
    int nsm = 0;
    cudaDeviceGetAttribute(&nsm, cudaDevAttrMultiProcessorCount, dev);
    if (nsm <= 0) nsm = 148;

    cudaFuncSetAttribute(mlp_scatter_kernel,
                         cudaFuncAttributeMaxDynamicSharedMemorySize,
                         SMEM_BYTES);
    mlp_scatter_kernel<<<nsm, 512, SMEM_BYTES>>>((const float4*)points,
                                                 (float*)d_out);
}